// round 7
// baseline (speedup 1.0000x reference)
#include <cuda_runtime.h>
#include <cuda_bf16.h>
#include <cuda_fp16.h>
#include <math.h>
#include <stdint.h>

#define BATCH 4
#define SQ    2048
#define SK    2048
#define NHEAD 8
#define MROWS (BATCH*SK)   // 8192
#define KPAD  640          // 576 padded to 128-multiple

#define Y_SCALE     131072.0f          // 2^17
#define INV_Y_SCALE 7.62939453125e-06f // 2^-17

// ---------------------------------------------------------------------------
// Device scratch
// ---------------------------------------------------------------------------
__device__ __align__(16) uint8_t g_KP8 [(long)MROWS*KPAD];
__device__ __align__(16) uint8_t g_Qb8 [(long)MROWS*512];
__device__ __align__(16) uint8_t g_w1t8[512*KPAD];
__device__ __align__(16) uint8_t g_w2t8[512*512];
__device__ __align__(16) uint8_t g_wqt8[512*512];
__device__ __align__(16) uint8_t g_wkt8[512*512];
__device__ __align__(16) uint8_t g_H8  [(long)MROWS*512];
__device__ __align__(16) uint8_t g_E8  [(long)MROWS*512];
__device__ __align__(16) __nv_bfloat16 g_Qp[(long)MROWS*512];   // (B,H,Sq,64)
__device__ __align__(16) __nv_bfloat16 g_Kp[(long)MROWS*512];   // (B,H,Sk,64)
__device__ __align__(16) uint8_t g_expS8[(long)BATCH*NHEAD*SQ*SK]; // e4m3(exp-1)
__device__ __align__(16) uint8_t g_y8  [(long)BATCH*SQ*SK];        // e4m3(y*2^17)
__device__ __align__(16) uint8_t g_valT8[(long)BATCH*512*2048];
__device__ float g_sv[BATCH*512];
__device__ float g_invZ[BATCH*SQ];
__device__ float g_headSum[(long)BATCH*NHEAD*SQ];

// ---------------------------------------------------------------------------
// Helpers
// ---------------------------------------------------------------------------
__device__ __forceinline__ uint32_t smem_u32(const void* p) {
    uint32_t a;
    asm("{ .reg .u64 t; cvta.to.shared.u64 t, %1; cvt.u32.u64 %0, t; }"
        : "=r"(a) : "l"(p));
    return a;
}
__device__ __forceinline__ void ldm_x4(uint32_t& r0, uint32_t& r1,
                                       uint32_t& r2, uint32_t& r3, uint32_t a) {
    asm volatile("ldmatrix.sync.aligned.m8n8.x4.shared.b16 {%0,%1,%2,%3}, [%4];"
                 : "=r"(r0), "=r"(r1), "=r"(r2), "=r"(r3) : "r"(a));
}
// fp8 e4m3 MMA, k32. Fragment layout == bf16 k16 layout in b16-element view.
__device__ __forceinline__ void mma16832(float* c, uint32_t a0, uint32_t a1,
                                         uint32_t a2, uint32_t a3,
                                         uint32_t b0, uint32_t b1) {
    asm volatile("mma.sync.aligned.m16n8k32.row.col.f32.e4m3.e4m3.f32 "
                 "{%0,%1,%2,%3},{%4,%5,%6,%7},{%8,%9},{%0,%1,%2,%3};"
                 : "+f"(c[0]), "+f"(c[1]), "+f"(c[2]), "+f"(c[3])
                 : "r"(a0), "r"(a1), "r"(a2), "r"(a3), "r"(b0), "r"(b1));
}
__device__ __forceinline__ void mma16816(float* c, uint32_t a0, uint32_t a1,
                                         uint32_t a2, uint32_t a3,
                                         uint32_t b0, uint32_t b1) {
    asm volatile("mma.sync.aligned.m16n8k16.row.col.f32.bf16.bf16.f32 "
                 "{%0,%1,%2,%3},{%4,%5,%6,%7},{%8,%9},{%0,%1,%2,%3};"
                 : "+f"(c[0]), "+f"(c[1]), "+f"(c[2]), "+f"(c[3])
                 : "r"(a0), "r"(a1), "r"(a2), "r"(a3), "r"(b0), "r"(b1));
}
#define CP_ASYNC16(dst, src) \
    asm volatile("cp.async.cg.shared.global [%0], [%1], 16;" :: "r"(dst), "l"(src))
#define CP_COMMIT() asm volatile("cp.async.commit_group;")
#define CP_WAIT(n)  asm volatile("cp.async.wait_group %0;" :: "n"(n))

__device__ __forceinline__ unsigned short f2_to_fp8x2(float hi, float lo) {
    unsigned short u;
    asm("cvt.rn.satfinite.e4m3x2.f32 %0, %1, %2;" : "=h"(u) : "f"(hi), "f"(lo));
    return u;
}
__device__ __forceinline__ float2 fp8x2_to_f2(unsigned short u) {
    uint32_t h2;
    asm("cvt.rn.f16x2.e4m3x2 %0, %1;" : "=r"(h2) : "h"(u));
    return __half22float2(*reinterpret_cast<__half2*>(&h2));
}
__device__ __forceinline__ uint32_t pack4_fp8(float a, float b, float c, float d) {
    unsigned short lo = f2_to_fp8x2(b, a);
    unsigned short hi = f2_to_fp8x2(d, c);
    return (uint32_t)lo | ((uint32_t)hi << 16);
}

// ---------------------------------------------------------------------------
// fp8 GEMM 128x128, BK=128 bytes: C = epi(A[M,K] @ Bt[N,K]^T)
//   256 threads, 8 warps (2m x 4n), 3-stage cp.async, 2 CTAs/SM.
// EPI: 0 relu+bias->fp8   1 tanh+bias->fp8   2 bias->bf16 head-split
//      4 (sv + acc*2^-17)*invZ -> fp32
// ---------------------------------------------------------------------------
#define STAGE_BYTES 36864            // A: 128*144, B: 128*144
#define GEMM_DYN (3*STAGE_BYTES)     // 110592

template<int EPI>
__global__ void __launch_bounds__(256, 2)
gemm128(const uint8_t* __restrict__ A,
        const uint8_t* __restrict__ Bt,
        const float* __restrict__ bias,
        void* __restrict__ Cout,
        int K, int S, long a_bstr, long b_bstr, long c_bstr,
        const float* __restrict__ sv,
        const float* __restrict__ rowinv)
{
    extern __shared__ __align__(16) char smem[];
    __shared__ float sbias[128];

    const int tid = threadIdx.x, lane = tid & 31, wid = tid >> 5;
    const int wm = wid >> 2, wn = wid & 3;          // 2 x 4 warps
    const int g = lane >> 2, tg = lane & 3;
    const int z = blockIdx.z;
    const int m0 = blockIdx.y * 128, n0 = blockIdx.x * 128;

    A  += (long)z * a_bstr;
    Bt += (long)z * b_bstr;

    if (tid < 128) {
        if (EPI <= 2) sbias[tid] = bias[n0 + tid];
        if (EPI == 4) sbias[tid] = sv[z*512 + n0 + tid];
    }

    float acc[4][4][4];
    #pragma unroll
    for (int i = 0; i < 4; i++)
        #pragma unroll
        for (int j = 0; j < 4; j++)
            #pragma unroll
            for (int r = 0; r < 4; r++) acc[i][j][r] = 0.f;

    const int nk = K >> 7;   // 128 fp8 per iter

    auto prefetch = [&](int t) {
        if (t >= nk) return;
        int kt = t * 128;
        char* base = smem + (t % 3) * STAGE_BYTES;
        #pragma unroll
        for (int i = 0; i < 4; i++) {                 // A: 128 rows x 8x16B
            int ch = tid + i*256;
            int r = ch >> 3, off = (ch & 7) * 16;
            CP_ASYNC16(smem_u32(base + r*144 + off),
                       A + (long)(m0 + r)*K + kt + off);
        }
        #pragma unroll
        for (int i = 0; i < 4; i++) {                 // B: 128 rows x 8x16B
            int ch = tid + i*256;
            int r = ch >> 3, off = (ch & 7) * 16;
            CP_ASYNC16(smem_u32(base + 18432 + r*144 + off),
                       Bt + (long)(n0 + r)*K + kt + off);
        }
    };

    prefetch(0); CP_COMMIT();
    prefetch(1); CP_COMMIT();

    // b16-element-view addressing (1 b16 = 2 fp8)
    const int arow = lane & 15;
    const int acol = (lane & 16) ? 8 : 0;
    const int brow = ((lane >> 4) & 1) * 8 + (lane & 7);
    const int bcol = ((lane >> 3) & 1) * 8;

    for (int t = 0; t < nk; ++t) {
        CP_WAIT(1);
        __syncthreads();
        prefetch(t + 2); CP_COMMIT();   // buffer freed at t-1, barrier-ordered
        char* base = smem + (t % 3) * STAGE_BYTES;
        #pragma unroll
        for (int ks = 0; ks < 4; ++ks) {   // 4 x k32
            uint32_t a[4][4], b[4][2];
            #pragma unroll
            for (int mi = 0; mi < 4; ++mi) {
                uint32_t ad = smem_u32(base + (wm*64 + mi*16 + arow)*144
                                            + (ks*16 + acol)*2);
                ldm_x4(a[mi][0], a[mi][1], a[mi][2], a[mi][3], ad);
            }
            #pragma unroll
            for (int p = 0; p < 2; ++p) {
                uint32_t bd = smem_u32(base + 18432 + (wn*32 + p*16 + brow)*144
                                             + (ks*16 + bcol)*2);
                ldm_x4(b[2*p][0], b[2*p][1], b[2*p+1][0], b[2*p+1][1], bd);
            }
            #pragma unroll
            for (int mi = 0; mi < 4; ++mi)
                #pragma unroll
                for (int nj = 0; nj < 4; ++nj)
                    mma16832(acc[mi][nj], a[mi][0], a[mi][1], a[mi][2], a[mi][3],
                             b[nj][0], b[nj][1]);
        }
    }

    // ---------------- epilogue ----------------
    #pragma unroll
    for (int mi = 0; mi < 4; ++mi) {
        #pragma unroll
        for (int half = 0; half < 2; ++half) {
            int m = m0 + wm*64 + mi*16 + g + half*8;
            float rz = (EPI == 4) ? rowinv[(long)z*SQ + m] : 0.f;
            #pragma unroll
            for (int nj = 0; nj < 4; ++nj) {
                int nl = wn*32 + nj*8 + tg*2;
                int n = n0 + nl;
                float v0 = acc[mi][nj][half*2 + 0];
                float v1 = acc[mi][nj][half*2 + 1];
                if (EPI <= 1) {
                    v0 += sbias[nl]; v1 += sbias[nl+1];
                    if (EPI == 0) { v0 = fmaxf(v0, 0.f); v1 = fmaxf(v1, 0.f); }
                    else          { v0 = tanhf(v0);      v1 = tanhf(v1); }
                    *(unsigned short*)&((uint8_t*)Cout)[(long)m*512 + n] =
                        f2_to_fp8x2(v1, v0);
                } else if (EPI == 2) {
                    v0 += sbias[nl]; v1 += sbias[nl+1];
                    __nv_bfloat162 pk;
                    pk.x = __float2bfloat16(v0); pk.y = __float2bfloat16(v1);
                    int b = m / S, srow = m - b*S;
                    int h = n >> 6, dd = n & 63;
                    long idx = (((long)(b*NHEAD + h)*S + srow) << 6) + dd;
                    *(__nv_bfloat162*)&((__nv_bfloat16*)Cout)[idx] = pk;
                } else { // EPI == 4
                    float o0 = (sbias[nl]   + v0 * INV_Y_SCALE) * rz;
                    float o1 = (sbias[nl+1] + v1 * INV_Y_SCALE) * rz;
                    *(float2*)&((float*)Cout)[(long)z*c_bstr + (long)m*512 + n] =
                        make_float2(o0, o1);
                }
            }
        }
    }
}

// ---------------------------------------------------------------------------
// Score GEMM (bf16, K=64 single-shot): exp(Qp·Kp^T/8); store fp8(e-1); rowsums
// ---------------------------------------------------------------------------
#define SC_DYN (2*128*144)

__global__ void __launch_bounds__(256)
score_mma(float* __restrict__ rowsum)
{
    extern __shared__ __align__(16) char smem[];
    __shared__ float srs[128];

    const int tid = threadIdx.x, lane = tid & 31, wid = tid >> 5;
    const int wm = wid >> 2, wn = wid & 3;
    const int g = lane >> 2, tg = lane & 3;
    const int z = blockIdx.z;
    const int m0 = blockIdx.y * 128, n0 = blockIdx.x * 128;

    const __nv_bfloat16* A  = g_Qp + (long)z * 2048 * 64;
    const __nv_bfloat16* Bt = g_Kp + (long)z * 2048 * 64;

    if (tid < 128) srs[tid] = 0.f;

    char* sA = smem;
    char* sB = smem + 128*144;
    #pragma unroll
    for (int i = 0; i < 4; i++) {
        int ch = tid + i*256;
        int r = ch >> 3, off = (ch & 7) * 8;
        CP_ASYNC16(smem_u32(sA + r*144 + off*2), A  + (long)(m0 + r)*64 + off);
        CP_ASYNC16(smem_u32(sB + r*144 + off*2), Bt + (long)(n0 + r)*64 + off);
    }
    CP_COMMIT();
    CP_WAIT(0);
    __syncthreads();

    const int arow = lane & 15;
    const int acol = (lane & 16) ? 8 : 0;
    const int brow = ((lane >> 4) & 1) * 8 + (lane & 7);
    const int bcol = ((lane >> 3) & 1) * 8;

    float acc[4][4][4];
    #pragma unroll
    for (int i = 0; i < 4; i++)
        #pragma unroll
        for (int j = 0; j < 4; j++)
            #pragma unroll
            for (int r = 0; r < 4; r++) acc[i][j][r] = 0.f;

    #pragma unroll
    for (int ks = 0; ks < 4; ++ks) {
        uint32_t a[4][4], b[4][2];
        #pragma unroll
        for (int mi = 0; mi < 4; ++mi) {
            uint32_t ad = smem_u32(sA + (wm*64 + mi*16 + arow)*144
                                      + (ks*16 + acol)*2);
            ldm_x4(a[mi][0], a[mi][1], a[mi][2], a[mi][3], ad);
        }
        #pragma unroll
        for (int p = 0; p < 2; ++p) {
            uint32_t bd = smem_u32(sB + (wn*32 + p*16 + brow)*144
                                      + (ks*16 + bcol)*2);
            ldm_x4(b[2*p][0], b[2*p][1], b[2*p+1][0], b[2*p+1][1], bd);
        }
        #pragma unroll
        for (int mi = 0; mi < 4; ++mi)
            #pragma unroll
            for (int nj = 0; nj < 4; ++nj)
                mma16816(acc[mi][nj], a[mi][0], a[mi][1], a[mi][2], a[mi][3],
                         b[nj][0], b[nj][1]);
    }

    #pragma unroll
    for (int mi = 0; mi < 4; ++mi) {
        #pragma unroll
        for (int half = 0; half < 2; ++half) {
            int m = m0 + wm*64 + mi*16 + g + half*8;
            float rsum = 0.f;
            #pragma unroll
            for (int nj = 0; nj < 4; ++nj) {
                int n = n0 + wn*32 + nj*8 + tg*2;
                float v0 = __expf(acc[mi][nj][half*2 + 0] * 0.125f);
                float v1 = __expf(acc[mi][nj][half*2 + 1] * 0.125f);
                rsum += v0 + v1;
                *(unsigned short*)&g_expS8[(long)z*SQ*SK + (long)m*2048 + n] =
                    f2_to_fp8x2(v1 - 1.f, v0 - 1.f);
            }
            rsum += __shfl_xor_sync(0xffffffffu, rsum, 1);
            rsum += __shfl_xor_sync(0xffffffffu, rsum, 2);
            if (tg == 0) atomicAdd(&srs[m - m0], rsum);
        }
    }
    __syncthreads();
    if (tid < 128) atomicAdd(&rowsum[(long)z*SQ + m0 + tid], srs[tid]);
}

// ---------------------------------------------------------------------------
// Prep + combine kernels
// ---------------------------------------------------------------------------
__global__ void zero_kernel() {
    int i = blockIdx.x * blockDim.x + threadIdx.x;
    if (i < BATCH*NHEAD*SQ) g_headSum[i] = 0.f;
    if (i < BATCH*512)      g_sv[i] = 0.f;
}

// concat(key, pe[kwpos], zero-pad) -> fp8 [MROWS, 640]
__global__ void convert_concat(const float* __restrict__ key,
                               const int* __restrict__ kwpos,
                               const float* __restrict__ pe)
{
    int i = blockIdx.x * blockDim.x + threadIdx.x;   // 4-elem chunk
    if (i >= MROWS * (KPAD/4)) return;
    int row = i / (KPAD/4), c4 = (i % (KPAD/4)) * 4;
    float4 v = make_float4(0.f, 0.f, 0.f, 0.f);
    if (c4 < 512) v = *(const float4*)&key[(long)row*512 + c4];
    else if (c4 < 576) { int p = kwpos[row]; v = *(const float4*)&pe[(long)p*64 + (c4-512)]; }
    *(uint32_t*)&g_KP8[(long)row*KPAD + c4] = pack4_fp8(v.x, v.y, v.z, v.w);
}

// fp32 -> fp8 flat (n4 = count/4)
__global__ void conv_fp8(const float* __restrict__ src,
                         uint8_t* __restrict__ dst, int n4)
{
    int i = blockIdx.x * blockDim.x + threadIdx.x;
    if (i >= n4) return;
    float4 v = *(const float4*)&src[(long)i*4];
    *(uint32_t*)&dst[(long)i*4] = pack4_fp8(v.x, v.y, v.z, v.w);
}

// transpose + fp8: dst[c][r]=fp8(src[r][c]) for r<Rsrc, 0 for r<Rdst; C mult 32
__global__ void transpose_fp8(const float* __restrict__ src,
                              uint8_t* __restrict__ dst,
                              int Rsrc, int Rdst, int C)
{
    __shared__ float t[32][33];
    int r0 = blockIdx.y * 32, c0 = blockIdx.x * 32;
    int tx = threadIdx.x & 31, ty = threadIdx.x >> 5;
    #pragma unroll
    for (int i = 0; i < 4; i++) {
        int r = r0 + ty + i*8;
        t[ty + i*8][tx] = (r < Rsrc) ? src[(long)r*C + c0 + tx] : 0.f;
    }
    __syncthreads();
    #pragma unroll
    for (int i = 0; i < 4; i++) {
        unsigned short u = f2_to_fp8x2(0.f, t[tx][ty + i*8]);
        dst[(long)(c0 + ty + i*8)*Rdst + r0 + tx] = (uint8_t)(u & 0xFF);
    }
}

// value transpose -> fp8 valT + fused fp32 column sums
__global__ void transpose_val(const float* __restrict__ value)
{
    __shared__ float t[32][33];
    int b = blockIdx.z;
    const float* src = value + (long)b*SK*512;
    uint8_t* dst = g_valT8 + (long)b*512*2048;
    int r0 = blockIdx.y * 32, c0 = blockIdx.x * 32;
    int tx = threadIdx.x & 31, ty = threadIdx.x >> 5;
    #pragma unroll
    for (int i = 0; i < 4; i++)
        t[ty + i*8][tx] = src[(long)(r0 + ty + i*8)*512 + c0 + tx];
    __syncthreads();
    #pragma unroll
    for (int i = 0; i < 4; i++) {
        unsigned short u = f2_to_fp8x2(0.f, t[tx][ty + i*8]);
        dst[(long)(c0 + ty + i*8)*2048 + r0 + tx] = (uint8_t)(u & 0xFF);
    }
    if (threadIdx.x < 32) {
        float s = 0.f;
        #pragma unroll
        for (int rl = 0; rl < 32; rl++) s += t[rl][threadIdx.x];
        atomicAdd(&g_sv[b*512 + c0 + threadIdx.x], s);
    }
}

// Combine: attn = c0 + (1/8)Σ_h s'_hk·invZ_h; e=exp(attn*dw);
// adjusted = e/Σe (fp32 out); y8 = fp8((e-1)*2^17); invZ = 1/Σe
__global__ void combine_kernel(const int* __restrict__ kwpos,
                               float* __restrict__ adj)
{
    int bq = blockIdx.x;
    int b  = bq >> 11;
    int q  = bq & 2047;
    int tid = threadIdx.x;
    int k0 = tid * 8;

    __shared__ float invHS[NHEAD];
    if (tid < NHEAD)
        invHS[tid] = 1.0f / g_headSum[(long)(b*NHEAD + tid)*SQ + q];
    __syncthreads();

    float c0 = 0.f;
    #pragma unroll
    for (int h = 0; h < NHEAD; h++) c0 += invHS[h];
    c0 *= 0.125f;

    float acc[8] = {0.f,0.f,0.f,0.f,0.f,0.f,0.f,0.f};
    #pragma unroll
    for (int h = 0; h < NHEAD; h++) {
        const uint8_t* rowp = g_expS8 + ((long)(b*NHEAD + h)*SQ + q)*SK + k0;
        uint2 raw = *(const uint2*)rowp;
        float w = invHS[h];
        float2 f0 = fp8x2_to_f2((unsigned short)(raw.x & 0xFFFF));
        float2 f1 = fp8x2_to_f2((unsigned short)(raw.x >> 16));
        float2 f2 = fp8x2_to_f2((unsigned short)(raw.y & 0xFFFF));
        float2 f3 = fp8x2_to_f2((unsigned short)(raw.y >> 16));
        acc[0] = fmaf(f0.x, w, acc[0]); acc[1] = fmaf(f0.y, w, acc[1]);
        acc[2] = fmaf(f1.x, w, acc[2]); acc[3] = fmaf(f1.y, w, acc[3]);
        acc[4] = fmaf(f2.x, w, acc[4]); acc[5] = fmaf(f2.y, w, acc[5]);
        acc[6] = fmaf(f3.x, w, acc[6]); acc[7] = fmaf(f3.y, w, acc[7]);
    }

    int4 kpa = *(const int4*)&kwpos[b*SK + k0];
    int4 kpb = *(const int4*)&kwpos[b*SK + k0 + 4];
    int kparr[8] = {kpa.x, kpa.y, kpa.z, kpa.w, kpb.x, kpb.y, kpb.z, kpb.w};

    float e[8];
    float sum = 0.f;
    #pragma unroll
    for (int i = 0; i < 8; i++) {
        float attn = fmaf(0.125f, acc[i], c0);
        float dw = 1.0f / (1.0f + fabsf((float)(q - kparr[i])));
        e[i] = __expf(attn * dw);
        sum += e[i];
    }

    #pragma unroll
    for (int s = 16; s > 0; s >>= 1) sum += __shfl_xor_sync(0xffffffffu, sum, s);
    __shared__ float wred[8];
    if ((tid & 31) == 0) wred[tid >> 5] = sum;
    __syncthreads();
    float tot = wred[0];
    #pragma unroll
    for (int w = 1; w < 8; w++) tot += wred[w];
    float inv = 1.0f / tot;
    if (tid == 0) g_invZ[bq] = inv;

    long base = (long)bq * SK;
    float av[8];
    #pragma unroll
    for (int i = 0; i < 8; i++) av[i] = e[i] * inv;
    *(float4*)&adj[base + k0]     = make_float4(av[0], av[1], av[2], av[3]);
    *(float4*)&adj[base + k0 + 4] = make_float4(av[4], av[5], av[6], av[7]);

    uint2 yp;
    yp.x = pack4_fp8((e[0]-1.f)*Y_SCALE, (e[1]-1.f)*Y_SCALE,
                     (e[2]-1.f)*Y_SCALE, (e[3]-1.f)*Y_SCALE);
    yp.y = pack4_fp8((e[4]-1.f)*Y_SCALE, (e[5]-1.f)*Y_SCALE,
                     (e[6]-1.f)*Y_SCALE, (e[7]-1.f)*Y_SCALE);
    *(uint2*)&g_y8[base + k0] = yp;
}

// ---------------------------------------------------------------------------
extern "C" void kernel_launch(void* const* d_in, const int* in_sizes, int n_in,
                              void* d_out, int out_size)
{
    const float* query   = (const float*)d_in[0];
    const float* key     = (const float*)d_in[1];
    const float* value   = (const float*)d_in[2];
    const int*   kwpos   = (const int*)  d_in[3];
    const float* pos_emb = (const float*)d_in[4];
    const float* w1      = (const float*)d_in[5];
    const float* b1      = (const float*)d_in[6];
    const float* w2      = (const float*)d_in[7];
    const float* b2      = (const float*)d_in[8];
    const float* wq      = (const float*)d_in[9];
    const float* bq      = (const float*)d_in[10];
    const float* wk      = (const float*)d_in[11];
    const float* bk      = (const float*)d_in[12];

    float* out = (float*)d_out;
    float* adj = out + (long)BATCH*SQ*512;

    void *gKP8, *gQb8, *gw1t8, *gw2t8, *gwqt8, *gwkt8, *gH8, *gE8,
         *gQp, *gKp, *gy8, *gvalT8, *gsv, *ghs, *ginvZ;
    cudaGetSymbolAddress(&gKP8,  g_KP8);
    cudaGetSymbolAddress(&gQb8,  g_Qb8);
    cudaGetSymbolAddress(&gw1t8, g_w1t8);
    cudaGetSymbolAddress(&gw2t8, g_w2t8);
    cudaGetSymbolAddress(&gwqt8, g_wqt8);
    cudaGetSymbolAddress(&gwkt8, g_wkt8);
    cudaGetSymbolAddress(&gH8,   g_H8);
    cudaGetSymbolAddress(&gE8,   g_E8);
    cudaGetSymbolAddress(&gQp,   g_Qp);
    cudaGetSymbolAddress(&gKp,   g_Kp);
    cudaGetSymbolAddress(&gy8,   g_y8);
    cudaGetSymbolAddress(&gvalT8,g_valT8);
    cudaGetSymbolAddress(&gsv,   g_sv);
    cudaGetSymbolAddress(&ghs,   g_headSum);
    cudaGetSymbolAddress(&ginvZ, g_invZ);

    cudaFuncSetAttribute(gemm128<0>, cudaFuncAttributeMaxDynamicSharedMemorySize, GEMM_DYN);
    cudaFuncSetAttribute(gemm128<1>, cudaFuncAttributeMaxDynamicSharedMemorySize, GEMM_DYN);
    cudaFuncSetAttribute(gemm128<2>, cudaFuncAttributeMaxDynamicSharedMemorySize, GEMM_DYN);
    cudaFuncSetAttribute(gemm128<4>, cudaFuncAttributeMaxDynamicSharedMemorySize, GEMM_DYN);
    cudaFuncSetAttribute(score_mma,  cudaFuncAttributeMaxDynamicSharedMemorySize, SC_DYN);

    // launch order: index 5 = gemm128<1> (E) for ncu -s 5
    zero_kernel<<<(BATCH*NHEAD*SQ + 255)/256, 256>>>();                        // 0
    convert_concat<<<(MROWS*(KPAD/4) + 255)/256, 256>>>(key, kwpos, pos_emb);  // 1
    transpose_fp8<<<dim3(16, 20, 1), 256>>>(w1, (uint8_t*)gw1t8, 576, KPAD, 512); // 2
    gemm128<0><<<dim3(4, 64, 1), 256, GEMM_DYN>>>(                             // 3: H
        (uint8_t*)gKP8, (uint8_t*)gw1t8, b1, gH8,
        KPAD, SK, 0, 0, 0, nullptr, nullptr);
    transpose_fp8<<<dim3(16, 16, 1), 256>>>(w2, (uint8_t*)gw2t8, 512, 512, 512); // 4
    gemm128<1><<<dim3(4, 64, 1), 256, GEMM_DYN>>>(                             // 5: E
        (uint8_t*)gH8, (uint8_t*)gw2t8, b2, gE8,
        512, SK, 0, 0, 0, nullptr, nullptr);
    transpose_fp8<<<dim3(16, 16, 1), 256>>>(wk, (uint8_t*)gwkt8, 512, 512, 512); // 6
    gemm128<2><<<dim3(4, 64, 1), 256, GEMM_DYN>>>(                             // 7: Kp
        (uint8_t*)gE8, (uint8_t*)gwkt8, bk, gKp,
        512, SK, 0, 0, 0, nullptr, nullptr);
    conv_fp8<<<(MROWS*512/4 + 255)/256, 256>>>(query, (uint8_t*)gQb8, MROWS*512/4); // 8
    transpose_fp8<<<dim3(16, 16, 1), 256>>>(wq, (uint8_t*)gwqt8, 512, 512, 512);    // 9
    gemm128<2><<<dim3(4, 64, 1), 256, GEMM_DYN>>>(                             // 10: Qp
        (uint8_t*)gQb8, (uint8_t*)gwqt8, bq, gQp,
        512, SQ, 0, 0, 0, nullptr, nullptr);
    score_mma<<<dim3(16, 16, BATCH*NHEAD), 256, SC_DYN>>>((float*)ghs);        // 11
    combine_kernel<<<BATCH*SQ, 256>>>(kwpos, adj);                             // 12
    transpose_val<<<dim3(16, 64, BATCH), 256>>>(value);                        // 13
    gemm128<4><<<dim3(4, 16, BATCH), 256, GEMM_DYN>>>(                         // 14: out
        (uint8_t*)gy8, (uint8_t*)gvalT8, nullptr, out,
        2048, SQ, (long)SQ*SK, (long)512*2048, (long)SQ*512,
        (const float*)gsv, (const float*)ginvZ);
}

// round 8
// speedup vs baseline: 1.0301x; 1.0301x over previous
#include <cuda_runtime.h>
#include <cuda_bf16.h>
#include <cuda_fp16.h>
#include <math.h>
#include <stdint.h>

#define BATCH 4
#define SQ    2048
#define SK    2048
#define NHEAD 8
#define MROWS (BATCH*SK)   // 8192
#define KPAD  640          // 576 padded to 128-multiple

#define Y_SCALE     131072.0f          // 2^17
#define INV_Y_SCALE 7.62939453125e-06f // 2^-17

// ---------------------------------------------------------------------------
// Device scratch
// ---------------------------------------------------------------------------
__device__ __align__(16) uint8_t g_KP8 [(long)MROWS*KPAD];
__device__ __align__(16) uint8_t g_Qb8 [(long)MROWS*512];
__device__ __align__(16) uint8_t g_w1t8[512*KPAD];
__device__ __align__(16) uint8_t g_w2t8[512*512];
__device__ __align__(16) uint8_t g_wqt8[512*512];
__device__ __align__(16) uint8_t g_wkt8[512*512];
__device__ __align__(16) uint8_t g_H8  [(long)MROWS*512];
__device__ __align__(16) uint8_t g_E8  [(long)MROWS*512];
__device__ __align__(16) __nv_bfloat16 g_Qp[(long)MROWS*512];   // (B,H,Sq,64)
__device__ __align__(16) __nv_bfloat16 g_Kp[(long)MROWS*512];   // (B,H,Sk,64)
__device__ __align__(16) uint8_t g_expS8[(long)BATCH*NHEAD*SQ*SK]; // e4m3(exp-1)
__device__ __align__(16) uint8_t g_y8  [(long)BATCH*SQ*SK];        // e4m3(y*2^17)
__device__ __align__(16) uint8_t g_valT8[(long)BATCH*512*2048];
__device__ float g_sv[BATCH*512];
__device__ float g_invZ[BATCH*SQ];
__device__ float g_headSum[(long)BATCH*NHEAD*SQ];

// ---------------------------------------------------------------------------
// Helpers
// ---------------------------------------------------------------------------
__device__ __forceinline__ uint32_t smem_u32(const void* p) {
    uint32_t a;
    asm("{ .reg .u64 t; cvta.to.shared.u64 t, %1; cvt.u32.u64 %0, t; }"
        : "=r"(a) : "l"(p));
    return a;
}
__device__ __forceinline__ void ldm_x4(uint32_t& r0, uint32_t& r1,
                                       uint32_t& r2, uint32_t& r3, uint32_t a) {
    asm volatile("ldmatrix.sync.aligned.m8n8.x4.shared.b16 {%0,%1,%2,%3}, [%4];"
                 : "=r"(r0), "=r"(r1), "=r"(r2), "=r"(r3) : "r"(a));
}
__device__ __forceinline__ void mma16832(float* c, uint32_t a0, uint32_t a1,
                                         uint32_t a2, uint32_t a3,
                                         uint32_t b0, uint32_t b1) {
    asm volatile("mma.sync.aligned.m16n8k32.row.col.f32.e4m3.e4m3.f32 "
                 "{%0,%1,%2,%3},{%4,%5,%6,%7},{%8,%9},{%0,%1,%2,%3};"
                 : "+f"(c[0]), "+f"(c[1]), "+f"(c[2]), "+f"(c[3])
                 : "r"(a0), "r"(a1), "r"(a2), "r"(a3), "r"(b0), "r"(b1));
}
__device__ __forceinline__ void mma16816(float* c, uint32_t a0, uint32_t a1,
                                         uint32_t a2, uint32_t a3,
                                         uint32_t b0, uint32_t b1) {
    asm volatile("mma.sync.aligned.m16n8k16.row.col.f32.bf16.bf16.f32 "
                 "{%0,%1,%2,%3},{%4,%5,%6,%7},{%8,%9},{%0,%1,%2,%3};"
                 : "+f"(c[0]), "+f"(c[1]), "+f"(c[2]), "+f"(c[3])
                 : "r"(a0), "r"(a1), "r"(a2), "r"(a3), "r"(b0), "r"(b1));
}
#define CP_ASYNC16(dst, src) \
    asm volatile("cp.async.cg.shared.global [%0], [%1], 16;" :: "r"(dst), "l"(src))
#define CP_COMMIT() asm volatile("cp.async.commit_group;")
#define CP_WAIT(n)  asm volatile("cp.async.wait_group %0;" :: "n"(n))

__device__ __forceinline__ unsigned short f2_to_fp8x2(float hi, float lo) {
    unsigned short u;
    asm("cvt.rn.satfinite.e4m3x2.f32 %0, %1, %2;" : "=h"(u) : "f"(hi), "f"(lo));
    return u;
}
__device__ __forceinline__ float2 fp8x2_to_f2(unsigned short u) {
    uint32_t h2;
    asm("cvt.rn.f16x2.e4m3x2 %0, %1;" : "=r"(h2) : "h"(u));
    return __half22float2(*reinterpret_cast<__half2*>(&h2));
}
__device__ __forceinline__ uint32_t pack4_fp8(float a, float b, float c, float d) {
    unsigned short lo = f2_to_fp8x2(b, a);
    unsigned short hi = f2_to_fp8x2(d, c);
    return (uint32_t)lo | ((uint32_t)hi << 16);
}

// SW128 swizzle: tile rows are 128B (8 x 16B chunks); chunk c of row r is
// stored at chunk (c ^ (r & 7)). Conflict-free for ldmatrix 8-row phases.
__device__ __forceinline__ uint32_t sw_off(int row, int chunk) {
    return (uint32_t)(row * 128 + ((chunk ^ (row & 7)) << 4));
}

// ---------------------------------------------------------------------------
// fp8 GEMM 128x128, BK=128 bytes, SW128-swizzled smem (conflict-free LDSM)
//   256 threads, 8 warps (2m x 4n), 3-stage cp.async, 2 CTAs/SM.
// EPI: 0 relu+bias->fp8   1 tanh+bias->fp8   2 bias->bf16 head-split
//      4 (sv + acc*2^-17)*invZ -> fp32
// ---------------------------------------------------------------------------
#define STAGE_BYTES 32768            // A: 128*128, B: 128*128
#define GEMM_DYN (3*STAGE_BYTES)     // 98304

template<int EPI>
__global__ void __launch_bounds__(256, 2)
gemm128(const uint8_t* __restrict__ A,
        const uint8_t* __restrict__ Bt,
        const float* __restrict__ bias,
        void* __restrict__ Cout,
        int K, int S, long a_bstr, long b_bstr, long c_bstr,
        const float* __restrict__ sv,
        const float* __restrict__ rowinv)
{
    extern __shared__ __align__(16) char smem[];
    __shared__ float sbias[128];

    const int tid = threadIdx.x, lane = tid & 31, wid = tid >> 5;
    const int wm = wid >> 2, wn = wid & 3;          // 2 x 4 warps
    const int g = lane >> 2, tg = lane & 3;
    const int z = blockIdx.z;
    const int m0 = blockIdx.y * 128, n0 = blockIdx.x * 128;

    A  += (long)z * a_bstr;
    Bt += (long)z * b_bstr;

    if (tid < 128) {
        if (EPI <= 2) sbias[tid] = bias[n0 + tid];
        if (EPI == 4) sbias[tid] = sv[z*512 + n0 + tid];
    }

    float acc[4][4][4];
    #pragma unroll
    for (int i = 0; i < 4; i++)
        #pragma unroll
        for (int j = 0; j < 4; j++)
            #pragma unroll
            for (int r = 0; r < 4; r++) acc[i][j][r] = 0.f;

    const int nk = K >> 7;   // 128 fp8 per iter

    auto prefetch = [&](int t) {
        if (t >= nk) return;
        int kt = t * 128;
        char* base  = smem + (t % 3) * STAGE_BYTES;
        char* baseB = base + 16384;
        #pragma unroll
        for (int i = 0; i < 4; i++) {                 // A: 128 rows x 8x16B
            int ch = tid + i*256;
            int r = ch >> 3, c = ch & 7;
            CP_ASYNC16(smem_u32(base + sw_off(r, c)),
                       A + (long)(m0 + r)*K + kt + c*16);
        }
        #pragma unroll
        for (int i = 0; i < 4; i++) {                 // B
            int ch = tid + i*256;
            int r = ch >> 3, c = ch & 7;
            CP_ASYNC16(smem_u32(baseB + sw_off(r, c)),
                       Bt + (long)(n0 + r)*K + kt + c*16);
        }
    };

    prefetch(0); CP_COMMIT();
    prefetch(1); CP_COMMIT();

    // b16-element-view fragment rows/cols (1 b16 = 2 fp8)
    const int arow = lane & 15;
    const int ach  = (lane & 16) ? 1 : 0;   // chunk sub-index from acol
    const int brow = ((lane >> 4) & 1) * 8 + (lane & 7);
    const int bch  = ((lane >> 3) & 1);

    for (int t = 0; t < nk; ++t) {
        CP_WAIT(1);
        __syncthreads();
        prefetch(t + 2); CP_COMMIT();   // buffer freed at t-1, barrier-ordered
        char* base  = smem + (t % 3) * STAGE_BYTES;
        char* baseB = base + 16384;
        #pragma unroll
        for (int ks = 0; ks < 4; ++ks) {   // 4 x k32
            uint32_t a[4][4], b[4][2];
            #pragma unroll
            for (int mi = 0; mi < 4; ++mi) {
                int R = wm*64 + mi*16 + arow;
                uint32_t ad = smem_u32(base + sw_off(R, 2*ks + ach));
                ldm_x4(a[mi][0], a[mi][1], a[mi][2], a[mi][3], ad);
            }
            #pragma unroll
            for (int p = 0; p < 2; ++p) {
                int R = wn*32 + p*16 + brow;
                uint32_t bd = smem_u32(baseB + sw_off(R, 2*ks + bch));
                ldm_x4(b[2*p][0], b[2*p][1], b[2*p+1][0], b[2*p+1][1], bd);
            }
            #pragma unroll
            for (int mi = 0; mi < 4; ++mi)
                #pragma unroll
                for (int nj = 0; nj < 4; ++nj)
                    mma16832(acc[mi][nj], a[mi][0], a[mi][1], a[mi][2], a[mi][3],
                             b[nj][0], b[nj][1]);
        }
    }

    // ---------------- epilogue ----------------
    #pragma unroll
    for (int mi = 0; mi < 4; ++mi) {
        #pragma unroll
        for (int half = 0; half < 2; ++half) {
            int m = m0 + wm*64 + mi*16 + g + half*8;
            float rz = (EPI == 4) ? rowinv[(long)z*SQ + m] : 0.f;
            #pragma unroll
            for (int nj = 0; nj < 4; ++nj) {
                int nl = wn*32 + nj*8 + tg*2;
                int n = n0 + nl;
                float v0 = acc[mi][nj][half*2 + 0];
                float v1 = acc[mi][nj][half*2 + 1];
                if (EPI <= 1) {
                    v0 += sbias[nl]; v1 += sbias[nl+1];
                    if (EPI == 0) { v0 = fmaxf(v0, 0.f); v1 = fmaxf(v1, 0.f); }
                    else          { v0 = tanhf(v0);      v1 = tanhf(v1); }
                    *(unsigned short*)&((uint8_t*)Cout)[(long)m*512 + n] =
                        f2_to_fp8x2(v1, v0);
                } else if (EPI == 2) {
                    v0 += sbias[nl]; v1 += sbias[nl+1];
                    __nv_bfloat162 pk;
                    pk.x = __float2bfloat16(v0); pk.y = __float2bfloat16(v1);
                    int b = m / S, srow = m - b*S;
                    int h = n >> 6, dd = n & 63;
                    long idx = (((long)(b*NHEAD + h)*S + srow) << 6) + dd;
                    *(__nv_bfloat162*)&((__nv_bfloat16*)Cout)[idx] = pk;
                } else { // EPI == 4
                    float o0 = (sbias[nl]   + v0 * INV_Y_SCALE) * rz;
                    float o1 = (sbias[nl+1] + v1 * INV_Y_SCALE) * rz;
                    *(float2*)&((float*)Cout)[(long)z*c_bstr + (long)m*512 + n] =
                        make_float2(o0, o1);
                }
            }
        }
    }
}

// ---------------------------------------------------------------------------
// Score GEMM (bf16, K=64 single-shot, SW128-swizzled): exp(Qp·Kp^T/8)
//   -> fp8(e-1); rowsums. Row = 64 bf16 = 128B exactly.
// ---------------------------------------------------------------------------
#define SC_DYN (2*128*128)

__global__ void __launch_bounds__(256)
score_mma(float* __restrict__ rowsum)
{
    extern __shared__ __align__(16) char smem[];
    __shared__ float srs[128];

    const int tid = threadIdx.x, lane = tid & 31, wid = tid >> 5;
    const int wm = wid >> 2, wn = wid & 3;
    const int g = lane >> 2, tg = lane & 3;
    const int z = blockIdx.z;
    const int m0 = blockIdx.y * 128, n0 = blockIdx.x * 128;

    const __nv_bfloat16* A  = g_Qp + (long)z * 2048 * 64;
    const __nv_bfloat16* Bt = g_Kp + (long)z * 2048 * 64;

    if (tid < 128) srs[tid] = 0.f;

    char* sA = smem;
    char* sB = smem + 16384;
    #pragma unroll
    for (int i = 0; i < 4; i++) {
        int ch = tid + i*256;
        int r = ch >> 3, c = ch & 7;
        CP_ASYNC16(smem_u32(sA + sw_off(r, c)), A  + (long)(m0 + r)*64 + c*8);
        CP_ASYNC16(smem_u32(sB + sw_off(r, c)), Bt + (long)(n0 + r)*64 + c*8);
    }
    CP_COMMIT();
    CP_WAIT(0);
    __syncthreads();

    const int arow = lane & 15;
    const int ach  = (lane & 16) ? 1 : 0;
    const int brow = ((lane >> 4) & 1) * 8 + (lane & 7);
    const int bch  = ((lane >> 3) & 1);

    float acc[4][4][4];
    #pragma unroll
    for (int i = 0; i < 4; i++)
        #pragma unroll
        for (int j = 0; j < 4; j++)
            #pragma unroll
            for (int r = 0; r < 4; r++) acc[i][j][r] = 0.f;

    #pragma unroll
    for (int ks = 0; ks < 4; ++ks) {
        uint32_t a[4][4], b[4][2];
        #pragma unroll
        for (int mi = 0; mi < 4; ++mi) {
            int R = wm*64 + mi*16 + arow;
            uint32_t ad = smem_u32(sA + sw_off(R, 2*ks + ach));
            ldm_x4(a[mi][0], a[mi][1], a[mi][2], a[mi][3], ad);
        }
        #pragma unroll
        for (int p = 0; p < 2; ++p) {
            int R = wn*32 + p*16 + brow;
            uint32_t bd = smem_u32(sB + sw_off(R, 2*ks + bch));
            ldm_x4(b[2*p][0], b[2*p][1], b[2*p+1][0], b[2*p+1][1], bd);
        }
        #pragma unroll
        for (int mi = 0; mi < 4; ++mi)
            #pragma unroll
            for (int nj = 0; nj < 4; ++nj)
                mma16816(acc[mi][nj], a[mi][0], a[mi][1], a[mi][2], a[mi][3],
                         b[nj][0], b[nj][1]);
    }

    #pragma unroll
    for (int mi = 0; mi < 4; ++mi) {
        #pragma unroll
        for (int half = 0; half < 2; ++half) {
            int m = m0 + wm*64 + mi*16 + g + half*8;
            float rsum = 0.f;
            #pragma unroll
            for (int nj = 0; nj < 4; ++nj) {
                int n = n0 + wn*32 + nj*8 + tg*2;
                float v0 = __expf(acc[mi][nj][half*2 + 0] * 0.125f);
                float v1 = __expf(acc[mi][nj][half*2 + 1] * 0.125f);
                rsum += v0 + v1;
                *(unsigned short*)&g_expS8[(long)z*SQ*SK + (long)m*2048 + n] =
                    f2_to_fp8x2(v1 - 1.f, v0 - 1.f);
            }
            rsum += __shfl_xor_sync(0xffffffffu, rsum, 1);
            rsum += __shfl_xor_sync(0xffffffffu, rsum, 2);
            if (tg == 0) atomicAdd(&srs[m - m0], rsum);
        }
    }
    __syncthreads();
    if (tid < 128) atomicAdd(&rowsum[(long)z*SQ + m0 + tid], srs[tid]);
}

// ---------------------------------------------------------------------------
// Prep + combine kernels
// ---------------------------------------------------------------------------
__global__ void zero_kernel() {
    int i = blockIdx.x * blockDim.x + threadIdx.x;
    if (i < BATCH*NHEAD*SQ) g_headSum[i] = 0.f;
    if (i < BATCH*512)      g_sv[i] = 0.f;
}

__global__ void convert_concat(const float* __restrict__ key,
                               const int* __restrict__ kwpos,
                               const float* __restrict__ pe)
{
    int i = blockIdx.x * blockDim.x + threadIdx.x;   // 4-elem chunk
    if (i >= MROWS * (KPAD/4)) return;
    int row = i / (KPAD/4), c4 = (i % (KPAD/4)) * 4;
    float4 v = make_float4(0.f, 0.f, 0.f, 0.f);
    if (c4 < 512) v = *(const float4*)&key[(long)row*512 + c4];
    else if (c4 < 576) { int p = kwpos[row]; v = *(const float4*)&pe[(long)p*64 + (c4-512)]; }
    *(uint32_t*)&g_KP8[(long)row*KPAD + c4] = pack4_fp8(v.x, v.y, v.z, v.w);
}

__global__ void conv_fp8(const float* __restrict__ src,
                         uint8_t* __restrict__ dst, int n4)
{
    int i = blockIdx.x * blockDim.x + threadIdx.x;
    if (i >= n4) return;
    float4 v = *(const float4*)&src[(long)i*4];
    *(uint32_t*)&dst[(long)i*4] = pack4_fp8(v.x, v.y, v.z, v.w);
}

__global__ void transpose_fp8(const float* __restrict__ src,
                              uint8_t* __restrict__ dst,
                              int Rsrc, int Rdst, int C)
{
    __shared__ float t[32][33];
    int r0 = blockIdx.y * 32, c0 = blockIdx.x * 32;
    int tx = threadIdx.x & 31, ty = threadIdx.x >> 5;
    #pragma unroll
    for (int i = 0; i < 4; i++) {
        int r = r0 + ty + i*8;
        t[ty + i*8][tx] = (r < Rsrc) ? src[(long)r*C + c0 + tx] : 0.f;
    }
    __syncthreads();
    #pragma unroll
    for (int i = 0; i < 4; i++) {
        unsigned short u = f2_to_fp8x2(0.f, t[tx][ty + i*8]);
        dst[(long)(c0 + ty + i*8)*Rdst + r0 + tx] = (uint8_t)(u & 0xFF);
    }
}

__global__ void transpose_val(const float* __restrict__ value)
{
    __shared__ float t[32][33];
    int b = blockIdx.z;
    const float* src = value + (long)b*SK*512;
    uint8_t* dst = g_valT8 + (long)b*512*2048;
    int r0 = blockIdx.y * 32, c0 = blockIdx.x * 32;
    int tx = threadIdx.x & 31, ty = threadIdx.x >> 5;
    #pragma unroll
    for (int i = 0; i < 4; i++)
        t[ty + i*8][tx] = src[(long)(r0 + ty + i*8)*512 + c0 + tx];
    __syncthreads();
    #pragma unroll
    for (int i = 0; i < 4; i++) {
        unsigned short u = f2_to_fp8x2(0.f, t[tx][ty + i*8]);
        dst[(long)(c0 + ty + i*8)*2048 + r0 + tx] = (uint8_t)(u & 0xFF);
    }
    if (threadIdx.x < 32) {
        float s = 0.f;
        #pragma unroll
        for (int rl = 0; rl < 32; rl++) s += t[rl][threadIdx.x];
        atomicAdd(&g_sv[b*512 + c0 + threadIdx.x], s);
    }
}

__global__ void combine_kernel(const int* __restrict__ kwpos,
                               float* __restrict__ adj)
{
    int bq = blockIdx.x;
    int b  = bq >> 11;
    int q  = bq & 2047;
    int tid = threadIdx.x;
    int k0 = tid * 8;

    __shared__ float invHS[NHEAD];
    if (tid < NHEAD)
        invHS[tid] = 1.0f / g_headSum[(long)(b*NHEAD + tid)*SQ + q];
    __syncthreads();

    float c0 = 0.f;
    #pragma unroll
    for (int h = 0; h < NHEAD; h++) c0 += invHS[h];
    c0 *= 0.125f;

    float acc[8] = {0.f,0.f,0.f,0.f,0.f,0.f,0.f,0.f};
    #pragma unroll
    for (int h = 0; h < NHEAD; h++) {
        const uint8_t* rowp = g_expS8 + ((long)(b*NHEAD + h)*SQ + q)*SK + k0;
        uint2 raw = *(const uint2*)rowp;
        float w = invHS[h];
        float2 f0 = fp8x2_to_f2((unsigned short)(raw.x & 0xFFFF));
        float2 f1 = fp8x2_to_f2((unsigned short)(raw.x >> 16));
        float2 f2 = fp8x2_to_f2((unsigned short)(raw.y & 0xFFFF));
        float2 f3 = fp8x2_to_f2((unsigned short)(raw.y >> 16));
        acc[0] = fmaf(f0.x, w, acc[0]); acc[1] = fmaf(f0.y, w, acc[1]);
        acc[2] = fmaf(f1.x, w, acc[2]); acc[3] = fmaf(f1.y, w, acc[3]);
        acc[4] = fmaf(f2.x, w, acc[4]); acc[5] = fmaf(f2.y, w, acc[5]);
        acc[6] = fmaf(f3.x, w, acc[6]); acc[7] = fmaf(f3.y, w, acc[7]);
    }

    int4 kpa = *(const int4*)&kwpos[b*SK + k0];
    int4 kpb = *(const int4*)&kwpos[b*SK + k0 + 4];
    int kparr[8] = {kpa.x, kpa.y, kpa.z, kpa.w, kpb.x, kpb.y, kpb.z, kpb.w};

    float e[8];
    float sum = 0.f;
    #pragma unroll
    for (int i = 0; i < 8; i++) {
        float attn = fmaf(0.125f, acc[i], c0);
        float dw = 1.0f / (1.0f + fabsf((float)(q - kparr[i])));
        e[i] = __expf(attn * dw);
        sum += e[i];
    }

    #pragma unroll
    for (int s = 16; s > 0; s >>= 1) sum += __shfl_xor_sync(0xffffffffu, sum, s);
    __shared__ float wred[8];
    if ((tid & 31) == 0) wred[tid >> 5] = sum;
    __syncthreads();
    float tot = wred[0];
    #pragma unroll
    for (int w = 1; w < 8; w++) tot += wred[w];
    float inv = 1.0f / tot;
    if (tid == 0) g_invZ[bq] = inv;

    long base = (long)bq * SK;
    float av[8];
    #pragma unroll
    for (int i = 0; i < 8; i++) av[i] = e[i] * inv;
    *(float4*)&adj[base + k0]     = make_float4(av[0], av[1], av[2], av[3]);
    *(float4*)&adj[base + k0 + 4] = make_float4(av[4], av[5], av[6], av[7]);

    uint2 yp;
    yp.x = pack4_fp8((e[0]-1.f)*Y_SCALE, (e[1]-1.f)*Y_SCALE,
                     (e[2]-1.f)*Y_SCALE, (e[3]-1.f)*Y_SCALE);
    yp.y = pack4_fp8((e[4]-1.f)*Y_SCALE, (e[5]-1.f)*Y_SCALE,
                     (e[6]-1.f)*Y_SCALE, (e[7]-1.f)*Y_SCALE);
    *(uint2*)&g_y8[base + k0] = yp;
}

// ---------------------------------------------------------------------------
extern "C" void kernel_launch(void* const* d_in, const int* in_sizes, int n_in,
                              void* d_out, int out_size)
{
    const float* query   = (const float*)d_in[0];
    const float* key     = (const float*)d_in[1];
    const float* value   = (const float*)d_in[2];
    const int*   kwpos   = (const int*)  d_in[3];
    const float* pos_emb = (const float*)d_in[4];
    const float* w1      = (const float*)d_in[5];
    const float* b1      = (const float*)d_in[6];
    const float* w2      = (const float*)d_in[7];
    const float* b2      = (const float*)d_in[8];
    const float* wq      = (const float*)d_in[9];
    const float* bq      = (const float*)d_in[10];
    const float* wk      = (const float*)d_in[11];
    const float* bk      = (const float*)d_in[12];

    float* out = (float*)d_out;
    float* adj = out + (long)BATCH*SQ*512;

    void *gKP8, *gQb8, *gw1t8, *gw2t8, *gwqt8, *gwkt8, *gH8, *gE8,
         *gQp, *gKp, *gy8, *gvalT8, *gsv, *ghs, *ginvZ;
    cudaGetSymbolAddress(&gKP8,  g_KP8);
    cudaGetSymbolAddress(&gQb8,  g_Qb8);
    cudaGetSymbolAddress(&gw1t8, g_w1t8);
    cudaGetSymbolAddress(&gw2t8, g_w2t8);
    cudaGetSymbolAddress(&gwqt8, g_wqt8);
    cudaGetSymbolAddress(&gwkt8, g_wkt8);
    cudaGetSymbolAddress(&gH8,   g_H8);
    cudaGetSymbolAddress(&gE8,   g_E8);
    cudaGetSymbolAddress(&gQp,   g_Qp);
    cudaGetSymbolAddress(&gKp,   g_Kp);
    cudaGetSymbolAddress(&gy8,   g_y8);
    cudaGetSymbolAddress(&gvalT8,g_valT8);
    cudaGetSymbolAddress(&gsv,   g_sv);
    cudaGetSymbolAddress(&ghs,   g_headSum);
    cudaGetSymbolAddress(&ginvZ, g_invZ);

    cudaFuncSetAttribute(gemm128<0>, cudaFuncAttributeMaxDynamicSharedMemorySize, GEMM_DYN);
    cudaFuncSetAttribute(gemm128<1>, cudaFuncAttributeMaxDynamicSharedMemorySize, GEMM_DYN);
    cudaFuncSetAttribute(gemm128<2>, cudaFuncAttributeMaxDynamicSharedMemorySize, GEMM_DYN);
    cudaFuncSetAttribute(gemm128<4>, cudaFuncAttributeMaxDynamicSharedMemorySize, GEMM_DYN);
    cudaFuncSetAttribute(score_mma,  cudaFuncAttributeMaxDynamicSharedMemorySize, SC_DYN);

    // launch order: index 5 = gemm128<1> (E) for ncu -s 5
    zero_kernel<<<(BATCH*NHEAD*SQ + 255)/256, 256>>>();                        // 0
    convert_concat<<<(MROWS*(KPAD/4) + 255)/256, 256>>>(key, kwpos, pos_emb);  // 1
    transpose_fp8<<<dim3(16, 20, 1), 256>>>(w1, (uint8_t*)gw1t8, 576, KPAD, 512); // 2
    gemm128<0><<<dim3(4, 64, 1), 256, GEMM_DYN>>>(                             // 3: H
        (uint8_t*)gKP8, (uint8_t*)gw1t8, b1, gH8,
        KPAD, SK, 0, 0, 0, nullptr, nullptr);
    transpose_fp8<<<dim3(16, 16, 1), 256>>>(w2, (uint8_t*)gw2t8, 512, 512, 512); // 4
    gemm128<1><<<dim3(4, 64, 1), 256, GEMM_DYN>>>(                             // 5: E
        (uint8_t*)gH8, (uint8_t*)gw2t8, b2, gE8,
        512, SK, 0, 0, 0, nullptr, nullptr);
    transpose_fp8<<<dim3(16, 16, 1), 256>>>(wk, (uint8_t*)gwkt8, 512, 512, 512); // 6
    gemm128<2><<<dim3(4, 64, 1), 256, GEMM_DYN>>>(                             // 7: Kp
        (uint8_t*)gE8, (uint8_t*)gwkt8, bk, gKp,
        512, SK, 0, 0, 0, nullptr, nullptr);
    conv_fp8<<<(MROWS*512/4 + 255)/256, 256>>>(query, (uint8_t*)gQb8, MROWS*512/4); // 8
    transpose_fp8<<<dim3(16, 16, 1), 256>>>(wq, (uint8_t*)gwqt8, 512, 512, 512);    // 9
    gemm128<2><<<dim3(4, 64, 1), 256, GEMM_DYN>>>(                             // 10: Qp
        (uint8_t*)gQb8, (uint8_t*)gwqt8, bq, gQp,
        512, SQ, 0, 0, 0, nullptr, nullptr);
    score_mma<<<dim3(16, 16, BATCH*NHEAD), 256, SC_DYN>>>((float*)ghs);        // 11
    combine_kernel<<<BATCH*SQ, 256>>>(kwpos, adj);                             // 12
    transpose_val<<<dim3(16, 64, BATCH), 256>>>(value);                        // 13
    gemm128<4><<<dim3(4, 16, BATCH), 256, GEMM_DYN>>>(                         // 14: out
        (uint8_t*)gy8, (uint8_t*)gvalT8, nullptr, out,
        2048, SQ, (long)SQ*SK, (long)512*2048, (long)SQ*512,
        (const float*)gsv, (const float*)ginvZ);
}